// round 17
// baseline (speedup 1.0000x reference)
#include <cuda_runtime.h>
#include <cuda_fp16.h>
#include <cstdint>

// ---------------------------------------------------------------------------
// Shapes (fixed by the dataset)
// ---------------------------------------------------------------------------
#define MB   4096
#define DIN  512
#define HID  2048

// ---------------------------------------------------------------------------
// Device scratch
// ---------------------------------------------------------------------------
__device__ __half g_x[(size_t)MB * DIN];
__device__ __half g_w1[(size_t)HID * DIN];
__device__ __half g_w2[(size_t)HID * HID];
__device__ __half g_h1[(size_t)MB * HID];
__device__ float g_scores[MB];

// ---------------------------------------------------------------------------
// Helpers
// ---------------------------------------------------------------------------
__device__ __forceinline__ uint32_t smem_u32(const void* p) {
    uint32_t a;
    asm("{ .reg .u64 t; cvta.to.shared.u64 t, %1; cvt.u32.u64 %0, t; }"
        : "=r"(a) : "l"(p));
    return a;
}

#define SW128(o) ((o) ^ (((o) >> 3) & 0x70))

#define CPA16(smem, gptr) \
    asm volatile("cp.async.cg.shared.global [%0], [%1], 16;" \
                 :: "r"(smem), "l"(gptr))

#define LDMX4(r0, r1, r2, r3, addr) \
    asm volatile("ldmatrix.sync.aligned.m8n8.x4.shared.b16 {%0,%1,%2,%3}, [%4];" \
                 : "=r"(r0), "=r"(r1), "=r"(r2), "=r"(r3) : "r"(addr))

#define MMAF16(c, a0, a1, a2, a3, b0, b1) \
    asm volatile("mma.sync.aligned.m16n8k16.row.col.f32.f16.f16.f32 " \
                 "{%0,%1,%2,%3}, {%4,%5,%6,%7}, {%8,%9}, {%0,%1,%2,%3};" \
                 : "+f"((c)[0]), "+f"((c)[1]), "+f"((c)[2]), "+f"((c)[3]) \
                 : "r"(a0), "r"(a1), "r"(a2), "r"(a3), "r"(b0), "r"(b1))

// float <-> ascending-sortable uint32
__device__ __forceinline__ uint32_t f2sort(float f) {
    uint32_t b = __float_as_uint(f);
    return (b & 0x80000000u) ? ~b : (b | 0x80000000u);
}
__device__ __forceinline__ float sort2f(uint32_t u) {
    uint32_t b = (u & 0x80000000u) ? (u ^ 0x80000000u) : ~u;
    return __uint_as_float(b);
}

// ---------------------------------------------------------------------------
// Fused prep kernel (unchanged from R15/R16)
// ---------------------------------------------------------------------------
#define XB  2048
#define T1B (HID / 64 * (DIN / 64))
#define T2B (HID / 64 * (HID / 64))
#define PREP_BLOCKS (XB + T1B + T2B + 4)

__device__ __forceinline__ void transpose_tile64(const float* __restrict__ W,
                                                 __half* __restrict__ T,
                                                 int K, int N,
                                                 int bx, int by, int tid,
                                                 float (*t)[65])
{
    const int n0 = bx * 64, k0 = by * 64;
    #pragma unroll
    for (int u = 0; u < 4; u++) {
        const int idx = u * 256 + tid;
        const int r  = idx >> 4;
        const int c4 = idx & 15;
        float4 v = *(const float4*)(W + (size_t)(k0 + r) * N + n0 + c4 * 4);
        t[r][c4 * 4 + 0] = v.x;
        t[r][c4 * 4 + 1] = v.y;
        t[r][c4 * 4 + 2] = v.z;
        t[r][c4 * 4 + 3] = v.w;
    }
    __syncthreads();
    #pragma unroll
    for (int u = 0; u < 8; u++) {
        const int idx = u * 256 + tid;
        const int nr = idx >> 5;
        const int kc = idx & 31;
        __half2 h;
        h.x = __float2half_rn(t[kc * 2][nr]);
        h.y = __float2half_rn(t[kc * 2 + 1][nr]);
        *(__half2*)(T + (size_t)(n0 + nr) * K + k0 + kc * 2) = h;
    }
}

__global__ __launch_bounds__(256)
void prep_kernel(const float* __restrict__ x,  __half* __restrict__ xh,
                 const float* __restrict__ W1, __half* __restrict__ w1t,
                 const float* __restrict__ W2, __half* __restrict__ w2t,
                 float* __restrict__ scores)
{
    __shared__ float t[64][65];
    const int b = blockIdx.x;
    const int tid = threadIdx.x;

    if (b < XB) {
        const int i = (b * 256 + tid) * 4;
        float4 v = *(const float4*)(x + i);
        __half2 a, c;
        a.x = __float2half_rn(v.x);
        a.y = __float2half_rn(v.y);
        c.x = __float2half_rn(v.z);
        c.y = __float2half_rn(v.w);
        *(__half2*)(xh + i)     = a;
        *(__half2*)(xh + i + 2) = c;
    } else if (b < XB + T1B) {
        const int lb = b - XB;
        transpose_tile64(W1, w1t, DIN, HID, lb & 31, lb >> 5, tid, t);
    } else if (b < XB + T1B + T2B) {
        const int lb = b - XB - T1B;
        transpose_tile64(W2, w2t, HID, HID, lb & 31, lb >> 5, tid, t);
    } else {
        const int lb = b - XB - T1B - T2B;
        scores[lb * 1024 + tid * 4 + 0] = 0.0f;
        scores[lb * 1024 + tid * 4 + 1] = 0.0f;
        scores[lb * 1024 + tid * 4 + 2] = 0.0f;
        scores[lb * 1024 + tid * 4 + 3] = 0.0f;
    }
}

// ---------------------------------------------------------------------------
// fp16 single-product GEMM (unchanged from R15/R16): CTA 128x128, 2 CTAs/SM.
// ---------------------------------------------------------------------------
#define BM 128
#define BN 128
#define KC 64
#define S_A 0
#define S_B 16384
#define STAGE_BYTES 32768
#define GEMM_SMEM (2 * STAGE_BYTES)

template<int MODE>
__global__ __launch_bounds__(256, 2)
void gemm_mma(const __half* __restrict__ A,
              const __half* __restrict__ B,
              const float* __restrict__ bias,
              int K, int Npitch,
              __half* __restrict__ outH,
              const float* __restrict__ w3,
              float* __restrict__ scores)
{
    extern __shared__ char smem[];
    const uint32_t sb = smem_u32(smem);

    const int tid   = threadIdx.x;
    const int lane  = tid & 31;
    const int w     = tid >> 5;
    const int warpM = w >> 2;
    const int warpN = w & 3;
    const int g     = lane >> 2;
    const int tig   = lane & 3;

    const int rowA0 = blockIdx.y * BM;
    const int colB0 = blockIdx.x * BN;
    const int nch   = K / KC;

    float acc[4][4][4];
    #pragma unroll
    for (int mf = 0; mf < 4; mf++)
        #pragma unroll
        for (int nf = 0; nf < 4; nf++)
            #pragma unroll
            for (int e = 0; e < 4; e++)
                acc[mf][nf][e] = 0.0f;

    auto load_chunk = [&](int j, int st) {
        const uint32_t stage = sb + st * STAGE_BYTES;
        const size_t cOff = (size_t)j * KC;
        #pragma unroll
        for (int u = 0; u < 8; u++) {
            const int seg  = u * 256 + tid;
            const int isB  = seg >> 10;
            const int r    = (seg & 1023) >> 3;
            const int s    = (seg & 7) << 4;
            const uint32_t sw = SW128(r * 128 + s);
            const __half* base = isB ? B : A;
            const int row0 = isB ? colB0 : rowA0;
            const char* gp = (const char*)(base + (size_t)(row0 + r) * K + cOff) + s;
            CPA16(stage + (isB ? S_B : S_A) + sw, gp);
        }
        asm volatile("cp.async.commit_group;");
    };

    const int aRow = warpM * 64 + (lane & 7) + ((lane >> 3) & 1) * 8;
    const int aKb  = ((lane >> 4) & 1) * 16;
    const int bRowBase = warpN * 32 + ((lane >> 4) & 1) * 8 + (lane & 7);
    const int bKb  = ((lane >> 3) & 1) * 16;

    load_chunk(0, 0);

    for (int j = 0; j < nch; j++) {
        __syncthreads();
        if (j + 1 < nch) {
            load_chunk(j + 1, (j + 1) & 1);
            asm volatile("cp.async.wait_group 1;" ::: "memory");
        } else {
            asm volatile("cp.async.wait_group 0;" ::: "memory");
        }
        __syncthreads();

        const uint32_t stage = sb + (j & 1) * STAGE_BYTES;

        #pragma unroll
        for (int ks = 0; ks < 4; ks++) {
            const int kbyte = ks * 32;
            uint32_t a[4][4];
            #pragma unroll
            for (int mf = 0; mf < 4; mf++) {
                const uint32_t off = SW128((aRow + mf * 16) * 128 + kbyte + aKb);
                LDMX4(a[mf][0], a[mf][1], a[mf][2], a[mf][3],
                      stage + S_A + off);
            }
            #pragma unroll
            for (int np = 0; np < 2; np++) {
                const uint32_t off = SW128((bRowBase + np * 16) * 128 + kbyte + bKb);
                uint32_t b0, b1, b2, b3r;
                LDMX4(b0, b1, b2, b3r, stage + S_B + off);
                #pragma unroll
                for (int mf = 0; mf < 4; mf++) {
                    MMAF16(acc[mf][2 * np],     a[mf][0], a[mf][1], a[mf][2], a[mf][3], b0, b1);
                    MMAF16(acc[mf][2 * np + 1], a[mf][0], a[mf][1], a[mf][2], a[mf][3], b2, b3r);
                }
            }
        }
    }

    if constexpr (MODE == 1) {
        #pragma unroll
        for (int mf = 0; mf < 4; mf++) {
            const int r0 = rowA0 + warpM * 64 + mf * 16 + g;
            const int r1 = r0 + 8;
            #pragma unroll
            for (int nf = 0; nf < 4; nf++) {
                const int col = colB0 + warpN * 32 + nf * 8 + tig * 2;
                const float bx = __ldg(bias + col);
                const float by = __ldg(bias + col + 1);
                __half2 h0, h1;
                h0.x = __float2half_rn(fmaxf(acc[mf][nf][0] + bx, 0.0f));
                h0.y = __float2half_rn(fmaxf(acc[mf][nf][1] + by, 0.0f));
                h1.x = __float2half_rn(fmaxf(acc[mf][nf][2] + bx, 0.0f));
                h1.y = __float2half_rn(fmaxf(acc[mf][nf][3] + by, 0.0f));
                *(__half2*)(outH + (size_t)r0 * Npitch + col) = h0;
                *(__half2*)(outH + (size_t)r1 * Npitch + col) = h1;
            }
        }
    } else {
        #pragma unroll
        for (int mf = 0; mf < 4; mf++) {
            const int r0 = rowA0 + warpM * 64 + mf * 16 + g;
            const int r1 = r0 + 8;
            float p0 = 0.0f, p1 = 0.0f;
            #pragma unroll
            for (int nf = 0; nf < 4; nf++) {
                const int col = colB0 + warpN * 32 + nf * 8 + tig * 2;
                const float bx = __ldg(bias + col);
                const float by = __ldg(bias + col + 1);
                const float wx = __ldg(w3 + col);
                const float wy = __ldg(w3 + col + 1);
                p0 += fmaxf(acc[mf][nf][0] + bx, 0.0f) * wx
                    + fmaxf(acc[mf][nf][1] + by, 0.0f) * wy;
                p1 += fmaxf(acc[mf][nf][2] + bx, 0.0f) * wx
                    + fmaxf(acc[mf][nf][3] + by, 0.0f) * wy;
            }
            p0 += __shfl_xor_sync(0xffffffffu, p0, 1);
            p0 += __shfl_xor_sync(0xffffffffu, p0, 2);
            p1 += __shfl_xor_sync(0xffffffffu, p1, 1);
            p1 += __shfl_xor_sync(0xffffffffu, p1, 2);
            if (tig == 0) {
                atomicAdd(scores + r0, p0);
                atomicAdd(scores + r1, p1);
            }
        }
    }
}

// ---------------------------------------------------------------------------
// soft_rank: packed-u64 hybrid bitonic sort + parallel PAV.
// Each element is (sortable_key << 32) | original_index in one uint64; every
// compare-exchange is 2 loads + 2 conditional stores (half of R16's traffic).
// Comparator predicates are identical to R16 (packed compare == key compare,
// idx bits only break exact ties).
// ---------------------------------------------------------------------------
__device__ __forceinline__ int pav_merge(int Lbase, int nl, int Rbase, int nr,
                                         int* __restrict__ pst,
                                         int* __restrict__ pcn,
                                         float* __restrict__ psm)
{
    int len = nl;
    for (int t = 0; t < nr; t++) {
        int   cs = pst[Rbase + t];
        int   cc = pcn[Rbase + t];
        float cm = psm[Rbase + t];
        while (len > 0) {
            float ts = psm[Lbase + len - 1];
            int   tc = pcn[Lbase + len - 1];
            if (ts * (float)cc < cm * (float)tc) {
                cm += ts; cc += tc; cs = pst[Lbase + len - 1];
                len--;
            } else break;
        }
        pst[Lbase + len] = cs;
        pcn[Lbase + len] = cc;
        psm[Lbase + len] = cm;
        len++;
    }
    return len;
}

__global__ void softrank_kernel(const float* __restrict__ scores,
                                const float* __restrict__ b3,
                                float* __restrict__ out,
                                int n)
{
    extern __shared__ unsigned long long kvs[];
    unsigned long long* kv = kvs;             // n  (32 KB)
    float* psm = (float*)(kv + n);            // n
    int*   pst = (int*)(psm + n);             // n
    int*   pcn = pst + n;                     // n
    int*   cA  = pcn + n;                     // n/2
    int*   cB  = cA + n / 2;                  // n/2

    const int tid  = threadIdx.x;
    const int nt   = blockDim.x;
    const int lane = tid & 31;
    const int wid  = tid >> 5;
    const float b3v = b3[0];

    for (int i = tid; i < n; i += nt) {
        float f = scores[i] + b3v;
        kv[i] = ((unsigned long long)f2sort(f) << 32) | (unsigned int)i;
    }
    __syncthreads();

    const int nseg = n >> 5;
    const int segs_per_warp = nseg / (nt >> 5);

    // ---- prologue: rounds k=2..32 in registers ----
    for (int q = 0; q < segs_per_warp; q++) {
        const int i = (wid * segs_per_warp + q) * 32 + lane;
        unsigned long long v = kv[i];
        #pragma unroll
        for (int k = 2; k <= 32; k <<= 1) {
            #pragma unroll
            for (int j = k >> 1; j > 0; j >>= 1) {
                unsigned long long pv = __shfl_xor_sync(0xffffffffu, v, j);
                const bool lower = (i & j) == 0;
                const bool up    = (i & k) == 0;
                const unsigned long long a = lower ? v : pv;
                const unsigned long long b = lower ? pv : v;
                const bool sw = up ? (a < b) : (a > b);
                if (sw) v = pv;
            }
        }
        kv[i] = v;
    }
    __syncthreads();

    // ---- rounds k=64..n ----
    for (int k = 64; k <= n; k <<= 1) {
        for (int j = k >> 1; j >= 32; j >>= 1) {
            for (int p = tid; p < n / 2; p += nt) {
                const int i   = ((p & ~(j - 1)) << 1) | (p & (j - 1));
                const int ixj = i + j;
                const bool up = (i & k) == 0;
                unsigned long long a = kv[i], b = kv[ixj];
                const bool sw = up ? (a < b) : (a > b);
                if (sw) { kv[i] = b; kv[ixj] = a; }
            }
            __syncthreads();
        }
        for (int q = 0; q < segs_per_warp; q++) {
            const int i = (wid * segs_per_warp + q) * 32 + lane;
            unsigned long long v = kv[i];
            const bool up = (i & k) == 0;
            #pragma unroll
            for (int j = 16; j > 0; j >>= 1) {
                unsigned long long pv = __shfl_xor_sync(0xffffffffu, v, j);
                const bool lower = (i & j) == 0;
                const unsigned long long a = lower ? v : pv;
                const unsigned long long b = lower ? pv : v;
                const bool sw = up ? (a < b) : (a > b);
                if (sw) v = pv;
            }
            kv[i] = v;
        }
        __syncthreads();
    }

    // ---- PAV level-0 pools: y[i] = s[i] - (n - i) ----
    for (int i = tid; i < n; i += nt) {
        pst[i] = i;
        pcn[i] = 1;
        psm[i] = sort2f((uint32_t)(kv[i] >> 32)) - (float)(n - i);
    }
    __syncthreads();

    for (int g2 = tid; g2 < n / 2; g2 += nt)
        cA[g2] = pav_merge(2 * g2, 1, 2 * g2 + 1, 1, pst, pcn, psm);
    __syncthreads();

    int* cCur = cA;
    int* cNxt = cB;
    for (int L = 2; (1 << L) <= n; L++) {
        const int half = 1 << (L - 1);
        const int nm = n >> L;
        for (int g2 = tid; g2 < nm; g2 += nt)
            cNxt[g2] = pav_merge((g2 << L), cCur[2 * g2],
                                 (g2 << L) + half, cCur[2 * g2 + 1],
                                 pst, pcn, psm);
        __syncthreads();
        int* t = cCur; cCur = cNxt; cNxt = t;
    }
    const int P = cCur[0];

    for (int i = tid; i < n; i += nt) {
        int lo = 0, hi = P - 1;
        while (lo < hi) {
            int mid = (lo + hi + 1) >> 1;
            if (pst[mid] <= i) lo = mid; else hi = mid - 1;
        }
        const float dual = psm[lo] / (float)pcn[lo];
        const unsigned long long e = kv[i];
        const float sv = sort2f((uint32_t)(e >> 32));
        out[(unsigned int)(e & 0xFFFFFFFFu)] = sv - dual;  // rank
        out[n + i] = scores[i] + b3v;                      // scores
    }
}

// ---------------------------------------------------------------------------
// Launch
// ---------------------------------------------------------------------------
extern "C" void kernel_launch(void* const* d_in, const int* in_sizes, int n_in,
                              void* d_out, int out_size)
{
    const float* x  = (const float*)d_in[0];
    const float* W1 = (const float*)d_in[1];
    const float* b1 = (const float*)d_in[2];
    const float* W2 = (const float*)d_in[3];
    const float* b2 = (const float*)d_in[4];
    const float* W3 = (const float*)d_in[5];
    const float* b3 = (const float*)d_in[6];
    float* out = (float*)d_out;

    __half *xh, *w1, *w2, *h1;
    float *sc;
    cudaGetSymbolAddress((void**)&xh, g_x);
    cudaGetSymbolAddress((void**)&w1, g_w1);
    cudaGetSymbolAddress((void**)&w2, g_w2);
    cudaGetSymbolAddress((void**)&h1, g_h1);
    cudaGetSymbolAddress((void**)&sc, g_scores);

    // one fused prep launch: convert x, transpose W1/W2, zero scores
    prep_kernel<<<PREP_BLOCKS, 256>>>(x, xh, W1, w1, W2, w2, sc);

    cudaFuncSetAttribute(gemm_mma<1>,
                         cudaFuncAttributeMaxDynamicSharedMemorySize, GEMM_SMEM);
    cudaFuncSetAttribute(gemm_mma<0>,
                         cudaFuncAttributeMaxDynamicSharedMemorySize, GEMM_SMEM);

    // layer 1: relu(x @ W1 + b1) -> h1 (fp16)
    {
        dim3 grid(HID / BN, MB / BM);
        gemm_mma<1><<<grid, 256, GEMM_SMEM>>>(xh, w1, b1, DIN, HID,
                                              h1, nullptr, nullptr);
    }
    // layer 2 + fused GEMV: scores = relu(h1 @ W2 + b2) @ W3
    {
        dim3 grid(HID / BN, MB / BM);
        gemm_mma<0><<<grid, 256, GEMM_SMEM>>>(h1, w2, b2, HID, HID,
                                              nullptr, W3, sc);
    }
    // soft_rank (+ b3): smem = 8n (kv) + 12n (psm/pst/pcn) + 4n (cA/cB) = 96KB
    {
        size_t smem = (size_t)MB * 24;
        cudaFuncSetAttribute(softrank_kernel,
                             cudaFuncAttributeMaxDynamicSharedMemorySize,
                             (int)smem);
        softrank_kernel<<<1, 1024, smem>>>(sc, b3, out, MB);
    }
}